// round 1
// baseline (speedup 1.0000x reference)
#include <cuda_runtime.h>
#include <math.h>

// Problem shape (fixed per reference):
//   x  : [32, 512, 56, 56] fp32
//   w1 : [32, 512] fp32   (Cr=32, C=512)
//   w2 : [512, 32] fp32
// Outputs (concatenated): scaled [32,512,56,56], comp [32,512]

#define B 32
#define C 512
#define CR 32
#define HW 3136            // 56*56
#define HW4 784            // HW/4
#define BC (B*C)           // 16384
#define NTOT (B*C*HW)      // 51380224
#define N4 (NTOT/4)        // 12845056

__device__ float g_y[BC];     // per-(b,c) mean of x
__device__ float g_gate[BC];  // sigmoid gate

// ---------------------------------------------------------------------------
// Kernel 1: y[bc] = mean over HW of x[bc, :]
// One block per (b,c). 256 threads, float4 loads.
// ---------------------------------------------------------------------------
__global__ __launch_bounds__(256) void k_reduce_mean(const float* __restrict__ x) {
    const int bc = blockIdx.x;
    const float4* __restrict__ xp = reinterpret_cast<const float4*>(x) + (size_t)bc * HW4;

    float s = 0.f;
    #pragma unroll 4
    for (int j = threadIdx.x; j < HW4; j += 256) {
        float4 v = xp[j];
        s += (v.x + v.y) + (v.z + v.w);
    }
    // warp reduce
    #pragma unroll
    for (int o = 16; o > 0; o >>= 1)
        s += __shfl_xor_sync(0xFFFFFFFFu, s, o);

    __shared__ float ws[8];
    const int lane = threadIdx.x & 31, wid = threadIdx.x >> 5;
    if (lane == 0) ws[wid] = s;
    __syncthreads();
    if (threadIdx.x == 0) {
        float t = 0.f;
        #pragma unroll
        for (int w = 0; w < 8; w++) t += ws[w];
        g_y[bc] = t * (1.0f / HW);
    }
}

// ---------------------------------------------------------------------------
// Kernel 2 (tiny): h = relu(y @ w1^T)  [32,32];  g = sigmoid(h @ w2^T) [32,512]
// Also: comp[b,c] = y[b,c] * (1 - g[b,c])  (algebraic identity — gate is
// constant over HW, so mean(x*(1-gate)) = (1-gate)*mean(x)).
// Single block of 1024 threads.
// ---------------------------------------------------------------------------
__global__ __launch_bounds__(1024) void k_se_mlp(const float* __restrict__ w1,
                                                 const float* __restrict__ w2,
                                                 float* __restrict__ comp_out) {
    __shared__ float h_s[B * CR];      // 4 KB
    __shared__ float y_s[BC > 12288 ? 1 : BC]; // placeholder (not used; y too big)

    const int tid = threadIdx.x;

    // h[b][r] = relu( sum_c y[b][c] * w1[r][c] ), one thread per (b,r)
    {
        const int b = tid >> 5;        // tid / 32
        const int r = tid & 31;        // tid % 32
        const float* yb = g_y + b * C;
        const float* w1r = w1 + r * C;
        float acc = 0.f;
        #pragma unroll 8
        for (int c = 0; c < C; c++) acc += yb[c] * w1r[c];
        h_s[tid] = fmaxf(acc, 0.f);
    }
    __syncthreads();

    // g[b][c] = sigmoid( sum_r h[b][r] * w2[c][r] ); 16384 entries / 1024 thr
    for (int idx = tid; idx < BC; idx += 1024) {
        const int b = idx >> 9;        // idx / 512
        const int c = idx & 511;       // idx % 512
        const float* hb = h_s + b * CR;
        const float* w2c = w2 + c * CR;
        float acc = 0.f;
        #pragma unroll
        for (int r = 0; r < CR; r++) acc += hb[r] * w2c[r];
        const float g = 1.0f / (1.0f + expf(-acc));
        g_gate[idx] = g;
        comp_out[idx] = g_y[idx] * (1.0f - g);
    }
    (void)y_s;
}

// ---------------------------------------------------------------------------
// Kernel 3: scaled = x * gate[bc], float4 elementwise. One float4 per thread.
// ---------------------------------------------------------------------------
__global__ __launch_bounds__(256) void k_apply_gate(const float* __restrict__ x,
                                                    float* __restrict__ out) {
    const int i = blockIdx.x * 256 + threadIdx.x;
    if (i >= N4) return;
    const int bc = i / HW4;
    const float g = __ldg(&g_gate[bc]);
    float4 v = reinterpret_cast<const float4*>(x)[i];
    v.x *= g; v.y *= g; v.z *= g; v.w *= g;
    reinterpret_cast<float4*>(out)[i] = v;
}

// ---------------------------------------------------------------------------
extern "C" void kernel_launch(void* const* d_in, const int* in_sizes, int n_in,
                              void* d_out, int out_size) {
    const float* x  = (const float*)d_in[0];
    const float* w1 = (const float*)d_in[1];
    const float* w2 = (const float*)d_in[2];
    float* out = (float*)d_out;

    float* scaled = out;             // [32,512,56,56]
    float* comp   = out + NTOT;      // [32,512]

    k_reduce_mean<<<BC, 256>>>(x);
    k_se_mlp<<<1, 1024>>>(w1, w2, comp);
    k_apply_gate<<<(N4 + 255) / 256, 256>>>(x, scaled);
}

// round 2
// speedup vs baseline: 3.4839x; 3.4839x over previous
#include <cuda_runtime.h>
#include <math.h>

// Problem shape (fixed per reference):
//   x  : [32, 512, 56, 56] fp32
//   w1 : [32, 512] fp32   (Cr=32, C=512)
//   w2 : [512, 32] fp32
// Outputs (concatenated): scaled [32,512,56,56], comp [32,512]

#define B 32
#define C 512
#define CR 32
#define HW 3136            // 56*56
#define HW4 784            // HW/4
#define BC (B*C)           // 16384
#define NTOT (B*C*HW)      // 51380224
#define N4 (NTOT/4)        // 12845056

__device__ float g_y[BC];      // per-(b,c) mean of x
__device__ float g_h[B * CR];  // hidden relu activations
__device__ float g_gate[BC];   // sigmoid gate

// ---------------------------------------------------------------------------
// Kernel 1: y[bc] = mean over HW of x[bc, :]
// One block per (b,c). 256 threads, float4 loads. Measured 5.06 TB/s.
// ---------------------------------------------------------------------------
__global__ __launch_bounds__(256) void k_reduce_mean(const float* __restrict__ x) {
    const int bc = blockIdx.x;
    const float4* __restrict__ xp = reinterpret_cast<const float4*>(x) + (size_t)bc * HW4;

    float s = 0.f;
    #pragma unroll 4
    for (int j = threadIdx.x; j < HW4; j += 256) {
        float4 v = xp[j];
        s += (v.x + v.y) + (v.z + v.w);
    }
    #pragma unroll
    for (int o = 16; o > 0; o >>= 1)
        s += __shfl_xor_sync(0xFFFFFFFFu, s, o);

    __shared__ float ws[8];
    const int lane = threadIdx.x & 31, wid = threadIdx.x >> 5;
    if (lane == 0) ws[wid] = s;
    __syncthreads();
    if (threadIdx.x == 0) {
        float t = 0.f;
        #pragma unroll
        for (int w = 0; w < 8; w++) t += ws[w];
        g_y[bc] = t * (1.0f / HW);
    }
}

// ---------------------------------------------------------------------------
// Kernel 2a: h[b][r] = relu( sum_c y[b][c] * w1[r][c] )
// One block per b (32 blocks), 1024 threads: warp = r, lanes stride over c.
// w1[r][c + lane] is fully coalesced; y[b][c] is a warp broadcast.
// ---------------------------------------------------------------------------
__global__ __launch_bounds__(1024) void k_h(const float* __restrict__ w1) {
    const int b = blockIdx.x;
    const int r = threadIdx.x >> 5;
    const int lane = threadIdx.x & 31;
    const float* __restrict__ yb  = g_y + b * C;
    const float* __restrict__ w1r = w1 + r * C;

    float acc = 0.f;
    #pragma unroll
    for (int c = lane; c < C; c += 32)
        acc += yb[c] * w1r[c];

    #pragma unroll
    for (int o = 16; o > 0; o >>= 1)
        acc += __shfl_xor_sync(0xFFFFFFFFu, acc, o);

    if (lane == 0) g_h[b * CR + r] = fmaxf(acc, 0.f);
}

// ---------------------------------------------------------------------------
// Kernel 2b: g[b][c] = sigmoid( sum_r h[b][r] * w2[c][r] );
//            comp[b][c] = y[b][c] * (1 - g)   (gate constant over H,W)
// 64 blocks x 256 threads, one thread per (b,c). h staged in smem (4KB);
// w2 row read as 8x float4 per thread (contiguous 128B per thread).
// ---------------------------------------------------------------------------
__global__ __launch_bounds__(256) void k_gate(const float* __restrict__ w2,
                                              float* __restrict__ comp_out) {
    __shared__ float h_s[B * CR];
    #pragma unroll
    for (int j = threadIdx.x; j < B * CR; j += 256)
        h_s[j] = g_h[j];
    __syncthreads();

    const int idx = blockIdx.x * 256 + threadIdx.x;   // 0..16383
    const int b = idx >> 9;        // / 512
    const int c = idx & 511;       // % 512
    const float* __restrict__ hb = h_s + b * CR;
    const float4* __restrict__ w2c = reinterpret_cast<const float4*>(w2 + c * CR);

    float acc = 0.f;
    #pragma unroll
    for (int j = 0; j < 8; j++) {
        float4 w = w2c[j];
        acc += hb[4*j+0] * w.x + hb[4*j+1] * w.y + hb[4*j+2] * w.z + hb[4*j+3] * w.w;
    }
    const float g = 1.0f / (1.0f + expf(-acc));
    g_gate[idx] = g;
    comp_out[idx] = g_y[idx] * (1.0f - g);
}

// ---------------------------------------------------------------------------
// Kernel 3: scaled = x * gate[bc], float4 elementwise.
// ---------------------------------------------------------------------------
__global__ __launch_bounds__(256) void k_apply_gate(const float* __restrict__ x,
                                                    float* __restrict__ out) {
    const int i = blockIdx.x * 256 + threadIdx.x;
    if (i >= N4) return;
    const int bc = i / HW4;
    const float g = __ldg(&g_gate[bc]);
    float4 v = reinterpret_cast<const float4*>(x)[i];
    v.x *= g; v.y *= g; v.z *= g; v.w *= g;
    reinterpret_cast<float4*>(out)[i] = v;
}

// ---------------------------------------------------------------------------
extern "C" void kernel_launch(void* const* d_in, const int* in_sizes, int n_in,
                              void* d_out, int out_size) {
    const float* x  = (const float*)d_in[0];
    const float* w1 = (const float*)d_in[1];
    const float* w2 = (const float*)d_in[2];
    float* out = (float*)d_out;

    float* scaled = out;             // [32,512,56,56]
    float* comp   = out + NTOT;      // [32,512]

    k_reduce_mean<<<BC, 256>>>(x);
    k_h<<<B, 1024>>>(w1);
    k_gate<<<BC / 256, 256>>>(w2, comp);
    k_apply_gate<<<(N4 + 255) / 256, 256>>>(x, scaled);
}

// round 3
// speedup vs baseline: 3.7551x; 1.0779x over previous
#include <cuda_runtime.h>
#include <math.h>

// x:[32,512,56,56] f32, w1:[32,512], w2:[512,32]
// out = concat(scaled [32,512,56,56], comp [32,512])

#define B 32
#define C 512
#define CR 32
#define HW 3136
#define HW4 784
#define BC (B*C)           // 16384
#define NTOT (B*C*HW)
#define N4 (NTOT/4)        // 12845056
#define N8 (N4/2)          // 6422528

__device__ float g_y[BC];
__device__ float g_gate[BC];

// ---------------------------------------------------------------------------
// Kernel 1: y[bc] = mean(x[bc,:]). One WARP per bc, 8 warps/block.
// Lane streams float4s with stride 32: 24 full iters + 16-lane tail.
// __ldcs: x has no reuse here.
// ---------------------------------------------------------------------------
__global__ __launch_bounds__(256) void k_reduce_mean(const float* __restrict__ x) {
    const int warp = threadIdx.x >> 5;
    const int lane = threadIdx.x & 31;
    const int bc = blockIdx.x * 8 + warp;
    const float4* __restrict__ xp = reinterpret_cast<const float4*>(x) + (size_t)bc * HW4;

    float s = 0.f;
    int j = lane;
    #pragma unroll 6
    for (int k = 0; k < 24; k++, j += 32) {
        float4 v = __ldcs(&xp[j]);
        s += (v.x + v.y) + (v.z + v.w);
    }
    if (lane < 16) {                       // 784 = 24*32 + 16
        float4 v = __ldcs(&xp[768 + lane]);
        s += (v.x + v.y) + (v.z + v.w);
    }
    #pragma unroll
    for (int o = 16; o > 0; o >>= 1)
        s += __shfl_xor_sync(0xFFFFFFFFu, s, o);
    if (lane == 0) g_y[bc] = s * (1.0f / HW);
}

// ---------------------------------------------------------------------------
// Kernel 2 (fused MLP): one block per b, 512 threads.
// Phase 1: h[r]=relu(sum_c y[b][c]*w1[r][c]); 16 warps, 2 r's per warp.
// Phase 2: g[b][c]=sigmoid(sum_r h[r]*w2[c][r]); one thread per c.
//          comp[b][c]=y[b][c]*(1-g)  (gate constant over H,W).
// ---------------------------------------------------------------------------
__global__ __launch_bounds__(512) void k_mlp(const float* __restrict__ w1,
                                             const float* __restrict__ w2,
                                             float* __restrict__ comp_out) {
    __shared__ float y_s[C];
    __shared__ float h_s[CR];
    const int b = blockIdx.x;
    const int tid = threadIdx.x;

    y_s[tid] = g_y[b * C + tid];           // 512 threads, 512 values
    __syncthreads();

    const int warp = tid >> 5;
    const int lane = tid & 31;
    #pragma unroll
    for (int r2 = 0; r2 < 2; r2++) {
        const int r = warp * 2 + r2;
        const float* __restrict__ w1r = w1 + r * C;
        float acc = 0.f;
        #pragma unroll
        for (int c = lane; c < C; c += 32)
            acc += y_s[c] * w1r[c];
        #pragma unroll
        for (int o = 16; o > 0; o >>= 1)
            acc += __shfl_xor_sync(0xFFFFFFFFu, acc, o);
        if (lane == 0) h_s[r] = fmaxf(acc, 0.f);
    }
    __syncthreads();

    const int c = tid;
    const float4* __restrict__ w2c = reinterpret_cast<const float4*>(w2 + c * CR);
    float acc = 0.f;
    #pragma unroll
    for (int j = 0; j < 8; j++) {
        float4 w = w2c[j];
        acc += h_s[4*j+0] * w.x + h_s[4*j+1] * w.y + h_s[4*j+2] * w.z + h_s[4*j+3] * w.w;
    }
    const float g = 1.0f / (1.0f + expf(-acc));
    const int idx = b * C + c;
    g_gate[idx] = g;
    comp_out[idx] = y_s[c] * (1.0f - g);
}

// ---------------------------------------------------------------------------
// Kernel 3: scaled = x * gate[bc]. Two float4s per thread (same bc — HW4 is
// even so a (2i,2i+1) pair never straddles a channel boundary).
// Streaming loads/stores: zero reuse on x and out.
// ---------------------------------------------------------------------------
__global__ __launch_bounds__(256) void k_apply_gate(const float* __restrict__ x,
                                                    float* __restrict__ out) {
    const int t = blockIdx.x * 256 + threadIdx.x;
    if (t >= N8) return;
    const int i = t * 2;
    const int bc = i / HW4;
    const float g = __ldg(&g_gate[bc]);

    const float4* __restrict__ xp = reinterpret_cast<const float4*>(x);
    float4* __restrict__ op = reinterpret_cast<float4*>(out);

    float4 v0 = __ldcs(&xp[i]);
    float4 v1 = __ldcs(&xp[i + 1]);
    v0.x *= g; v0.y *= g; v0.z *= g; v0.w *= g;
    v1.x *= g; v1.y *= g; v1.z *= g; v1.w *= g;
    __stcs(&op[i],     v0);
    __stcs(&op[i + 1], v1);
}

// ---------------------------------------------------------------------------
extern "C" void kernel_launch(void* const* d_in, const int* in_sizes, int n_in,
                              void* d_out, int out_size) {
    const float* x  = (const float*)d_in[0];
    const float* w1 = (const float*)d_in[1];
    const float* w2 = (const float*)d_in[2];
    float* out = (float*)d_out;

    float* scaled = out;
    float* comp   = out + NTOT;

    k_reduce_mean<<<BC / 8, 256>>>(x);
    k_mlp<<<B, 512>>>(w1, w2, comp);
    k_apply_gate<<<(N8 + 255) / 256, 256>>>(x, scaled);
}